// round 14
// baseline (speedup 1.0000x reference)
#include <cuda_runtime.h>
#include <cuda_bf16.h>
#include <math.h>
#include <stdint.h>

#define N_NODES 100000
#define N_EDGES 1600000
#define DIM 128
#define SCAN_BLK 1024
#define NBLK ((N_NODES + SCAN_BLK - 1) / SCAN_BLK)   // 98
#define GEMM_BLOCKS_TOTAL 782
#define NCHUNK 4

// ---------------- scratch (device globals; no allocations allowed) -------------
__device__ int   g_is64;
__device__ int   g_cnt[N_NODES];
__device__ int   g_cur[N_NODES];
__device__ int   g_tmp[N_NODES];
__device__ int   g_blocksum[128];
__device__ int   g_rowptr[N_NODES + 1];
__device__ int   g_perm[N_EDGES];
__device__ float g_deginv[N_NODES];
__device__ float g_agg[(size_t)N_NODES * DIM];
__device__ float g_h1[(size_t)N_NODES * DIM];
__device__ float g_wt1[128 * 256];
__device__ float g_wt2[128 * 256];
__device__ float g_p[N_NODES * 2];
__device__ float g_q[N_NODES * 2];

__device__ __forceinline__ float cvt_tf32(float x) {
    float r; asm("cvt.rna.tf32.f32 %0, %1;" : "=f"(r) : "f"(x)); return r;
}

// ---------------- CSR build --------------------------------------------------
__global__ void k_zero_counts(const int* __restrict__ ei32) {
    int i = blockIdx.x * blockDim.x + threadIdx.x;
    if (i < N_NODES) { g_cnt[i] = 0; g_cur[i] = 0; }
    if (blockIdx.x == 0) {
        __shared__ int nz;
        if (threadIdx.x == 0) nz = 0;
        __syncthreads();
        for (int j = threadIdx.x; j < 4096; j += blockDim.x)
            if (ei32[2 * j + 1] != 0) nz = 1;
        __syncthreads();
        if (threadIdx.x == 0) g_is64 = (nz == 0) ? 1 : 0;
    }
}

__global__ void k_hist(const void* __restrict__ ei) {
    int q = blockIdx.x * blockDim.x + threadIdx.x;
    int e0 = q * 4;
    if (e0 >= N_EDGES) return;
    if (g_is64) {
        const long long* p = (const long long*)ei + N_EDGES + e0;
        atomicAdd(&g_cnt[(int)p[0]], 1);
        atomicAdd(&g_cnt[(int)p[1]], 1);
        atomicAdd(&g_cnt[(int)p[2]], 1);
        atomicAdd(&g_cnt[(int)p[3]], 1);
    } else {
        int4 d = ((const int4*)((const int*)ei + N_EDGES))[q];
        atomicAdd(&g_cnt[d.x], 1);
        atomicAdd(&g_cnt[d.y], 1);
        atomicAdd(&g_cnt[d.z], 1);
        atomicAdd(&g_cnt[d.w], 1);
    }
}

__global__ void k_scan_a() {
    __shared__ int wsum[32];
    int tid = threadIdx.x;
    int lane = tid & 31, warp = tid >> 5;
    int i = blockIdx.x * SCAN_BLK + tid;
    int v = (i < N_NODES) ? g_cnt[i] : 0;
    int x = v;
#pragma unroll
    for (int off = 1; off < 32; off <<= 1) {
        int y = __shfl_up_sync(0xffffffffu, x, off);
        if (lane >= off) x += y;
    }
    if (lane == 31) wsum[warp] = x;
    __syncthreads();
    if (warp == 0) {
        int w = wsum[lane];
        int xw = w;
#pragma unroll
        for (int off = 1; off < 32; off <<= 1) {
            int y = __shfl_up_sync(0xffffffffu, xw, off);
            if (lane >= off) xw += y;
        }
        wsum[lane] = xw - w;
    }
    __syncthreads();
    int excl = x - v + wsum[warp];
    if (i < N_NODES) g_tmp[i] = excl;
    if (tid == SCAN_BLK - 1) g_blocksum[blockIdx.x] = excl + v;
}

__global__ void k_scan_c() {
    __shared__ int wred[32];
    __shared__ int sboff;
    int tid = threadIdx.x;
    int lane = tid & 31, warp = tid >> 5;
    int part = (tid < blockIdx.x) ? g_blocksum[tid] : 0;
#pragma unroll
    for (int off = 16; off > 0; off >>= 1)
        part += __shfl_down_sync(0xffffffffu, part, off);
    if (lane == 0) wred[warp] = part;
    __syncthreads();
    if (warp == 0) {
        int s = wred[lane];
#pragma unroll
        for (int off = 16; off > 0; off >>= 1)
            s += __shfl_down_sync(0xffffffffu, s, off);
        if (lane == 0) sboff = s;
    }
    __syncthreads();
    int i = blockIdx.x * SCAN_BLK + tid;
    if (i < N_NODES) {
        g_rowptr[i] = g_tmp[i] + sboff;
        g_deginv[i] = 1.0f / (float)max(g_cnt[i], 1);
    }
    if (i == 0) g_rowptr[N_NODES] = N_EDGES;
}

__global__ void k_perm(const void* __restrict__ ei) {
    int q = blockIdx.x * blockDim.x + threadIdx.x;
    int e0 = q * 4;
    if (e0 >= N_EDGES) return;
    if (g_is64) {
        const long long* ps = (const long long*)ei + e0;
        const long long* pd = (const long long*)ei + N_EDGES + e0;
#pragma unroll
        for (int j = 0; j < 4; j++) {
            int s = (int)ps[j], d = (int)pd[j];
            int pos = g_rowptr[d] + atomicAdd(&g_cur[d], 1);
            g_perm[pos] = s;
        }
    } else {
        int4 sv = ((const int4*)ei)[q];
        int4 dv = ((const int4*)((const int*)ei + N_EDGES))[q];
        int ss[4] = {sv.x, sv.y, sv.z, sv.w};
        int dd[4] = {dv.x, dv.y, dv.z, dv.w};
#pragma unroll
        for (int j = 0; j < 4; j++) {
            int pos = g_rowptr[dd[j]] + atomicAdd(&g_cur[dd[j]], 1);
            g_perm[pos] = ss[j];
        }
    }
}

// ---------------- weight transpose + stack (tf32 pre-rounded) -----------------
__global__ void k_wt(const float* __restrict__ Wl, const float* __restrict__ Wr,
                     float* __restrict__ Wt) {
    int idx = blockIdx.x * blockDim.x + threadIdx.x;
    if (idx < 128 * 128) {
        int k = idx >> 7, n = idx & 127;
        Wt[n * 256 + k]       = cvt_tf32(Wl[k * 128 + n]);
        Wt[n * 256 + 128 + k] = cvt_tf32(Wr[k * 128 + n]);
    }
}

// ---------------- gather-aggregate (warp per node, chunked) -------------------
__global__ void k_gather(const float* __restrict__ feat, float* __restrict__ out,
                         int node_base, int node_end) {
    int warp = node_base + ((blockIdx.x * blockDim.x + threadIdx.x) >> 5);
    int lane = threadIdx.x & 31;
    if (warp >= node_end) return;
    int s0 = g_rowptr[warp];
    int s1 = g_rowptr[warp + 1];
    float4 acc = make_float4(0.f, 0.f, 0.f, 0.f);
    int e = s0;
    for (; e + 1 < s1; e += 2) {
        int sa = __ldg(&g_perm[e]);
        int sb = __ldg(&g_perm[e + 1]);
        float4 va = *(const float4*)(feat + (size_t)sa * DIM + lane * 4);
        float4 vb = *(const float4*)(feat + (size_t)sb * DIM + lane * 4);
        acc.x += va.x; acc.y += va.y; acc.z += va.z; acc.w += va.w;
        acc.x += vb.x; acc.y += vb.y; acc.z += vb.z; acc.w += vb.w;
    }
    if (e < s1) {
        int sa = __ldg(&g_perm[e]);
        float4 va = *(const float4*)(feat + (size_t)sa * DIM + lane * 4);
        acc.x += va.x; acc.y += va.y; acc.z += va.z; acc.w += va.w;
    }
    float di = g_deginv[warp];
    float4 o;
    o.x = cvt_tf32(acc.x * di); o.y = cvt_tf32(acc.y * di);
    o.z = cvt_tf32(acc.z * di); o.w = cvt_tf32(acc.w * di);
    *(float4*)(out + (size_t)warp * DIM + lane * 4) = o;
}

// ---------------- tf32 mma.sync GEMM with cp.async double buffering ----------
#define ASTRIDE 36
#define BUF_FLOATS (128 * ASTRIDE)
#define GSM_FLOATS (4 * BUF_FLOATS + 128)
#define GSM_BYTES (GSM_FLOATS * 4)

__device__ __forceinline__ void cp16(uint32_t dst, const void* src, uint32_t srcsz) {
    asm volatile("cp.async.ca.shared.global [%0], [%1], 16, %2;"
                 :: "r"(dst), "l"(src), "r"(srcsz) : "memory");
}
__device__ __forceinline__ void cp_commit() {
    asm volatile("cp.async.commit_group;" ::: "memory");
}
template <int N>
__device__ __forceinline__ void cp_wait() {
    asm volatile("cp.async.wait_group %0;" :: "n"(N) : "memory");
}

__device__ __forceinline__ void mma_tf32(float* c, uint32_t a0, uint32_t a1,
                                         uint32_t a2, uint32_t a3,
                                         uint32_t b0, uint32_t b1) {
    asm volatile(
        "mma.sync.aligned.m16n8k8.row.col.f32.tf32.tf32.f32 "
        "{%0,%1,%2,%3}, {%4,%5,%6,%7}, {%8,%9}, {%0,%1,%2,%3};"
        : "+f"(c[0]), "+f"(c[1]), "+f"(c[2]), "+f"(c[3])
        : "r"(a0), "r"(a1), "r"(a2), "r"(a3), "r"(b0), "r"(b1));
}

__global__ void __launch_bounds__(256, 2)
k_gemm_mma(const float* __restrict__ Aagg, const float* __restrict__ Ax,
           const float* __restrict__ Wt, const float* __restrict__ bias,
           float* __restrict__ out,
           const float* __restrict__ W3l, const float* __restrict__ W3r,
           const float* __restrict__ b3,
           float* __restrict__ p_out, float* __restrict__ q_out,
           int fuse_pq, int blk_base) {
    extern __shared__ float sm[];
    float* Abuf = sm;
    float* Bbuf = sm + 2 * BUF_FLOATS;
    float* sbias = sm + 4 * BUF_FLOATS;

    int tid = threadIdx.x;
    int wid = tid >> 5, lane = tid & 31;
    int g = lane >> 2, t = lane & 3;
    int warp_m = (wid >> 2) * 64;
    int warp_n = (wid & 3) * 32;
    int row_base = (blockIdx.x + blk_base) * 128;

    if (tid < 128) sbias[tid] = bias[tid];

    uint32_t a_sm_base = (uint32_t)__cvta_generic_to_shared(Abuf);
    uint32_t b_sm_base = (uint32_t)__cvta_generic_to_shared(Bbuf);

    int lrow[4], lseg[4];
#pragma unroll
    for (int i = 0; i < 4; i++) {
        int f = tid + i * 256;
        lrow[i] = f >> 3;
        lseg[i] = f & 7;
    }

    auto issue = [&](int ch, int s) {
        int k0 = ch * 32;
        const float* Asrc = (k0 < 128) ? Aagg : Ax;
        int kbase = k0 & 127;
        uint32_t ao = a_sm_base + (uint32_t)(s * BUF_FLOATS * 4);
        uint32_t bo = b_sm_base + (uint32_t)(s * BUF_FLOATS * 4);
#pragma unroll
        for (int i = 0; i < 4; i++) {
            int row = lrow[i], seg = lseg[i];
            int gr = row_base + row;
            int ok = gr < N_NODES;
            const float* src = Asrc + (size_t)(ok ? gr : 0) * DIM + kbase + seg * 4;
            cp16(ao + (uint32_t)((row * ASTRIDE + seg * 4) * 4), src, ok ? 16u : 0u);
        }
#pragma unroll
        for (int i = 0; i < 4; i++) {
            int row = lrow[i], seg = lseg[i];
            const float* src = Wt + (size_t)row * 256 + k0 + seg * 4;
            cp16(bo + (uint32_t)((row * ASTRIDE + seg * 4) * 4), src, 16u);
        }
        cp_commit();
    };

    float acc[4][4][4];
#pragma unroll
    for (int i = 0; i < 4; i++)
#pragma unroll
        for (int j = 0; j < 4; j++)
#pragma unroll
            for (int q = 0; q < 4; q++) acc[i][j][q] = 0.f;

    issue(0, 0);

    for (int ch = 0; ch < 8; ch++) {
        int s = ch & 1;
        if (ch < 7) issue(ch + 1, s ^ 1);
        if (ch < 7) cp_wait<1>(); else cp_wait<0>();
        __syncthreads();

        const float* As = Abuf + s * BUF_FLOATS;
        const float* Bs = Bbuf + s * BUF_FLOATS;
#pragma unroll
        for (int kk = 0; kk < 4; kk++) {
            int kof = kk * 8;
            uint32_t af[4][4];
#pragma unroll
            for (int mi = 0; mi < 4; mi++) {
                const float* ap = As + (warp_m + mi * 16 + g) * ASTRIDE + kof + t;
                af[mi][0] = __float_as_uint(ap[0]);
                af[mi][1] = __float_as_uint(ap[8 * ASTRIDE]);
                af[mi][2] = __float_as_uint(ap[4]);
                af[mi][3] = __float_as_uint(ap[8 * ASTRIDE + 4]);
            }
            uint32_t bf[4][2];
#pragma unroll
            for (int ni = 0; ni < 4; ni++) {
                const float* bp = Bs + (warp_n + ni * 8 + g) * ASTRIDE + kof + t;
                bf[ni][0] = __float_as_uint(bp[0]);
                bf[ni][1] = __float_as_uint(bp[4]);
            }
#pragma unroll
            for (int mi = 0; mi < 4; mi++)
#pragma unroll
                for (int ni = 0; ni < 4; ni++)
                    mma_tf32(acc[mi][ni], af[mi][0], af[mi][1], af[mi][2], af[mi][3],
                             bf[ni][0], bf[ni][1]);
        }
        __syncthreads();
    }

    if (!fuse_pq) {
#pragma unroll
        for (int mi = 0; mi < 4; mi++) {
            int r0 = row_base + warp_m + mi * 16 + g;
            int r1 = r0 + 8;
#pragma unroll
            for (int ni = 0; ni < 4; ni++) {
                int c0 = warp_n + ni * 8 + t * 2;
                float b0 = sbias[c0], b1 = sbias[c0 + 1];
                if (r0 < N_NODES) {
                    float2 v = make_float2(fmaxf(acc[mi][ni][0] + b0, 0.f),
                                           fmaxf(acc[mi][ni][1] + b1, 0.f));
                    *(float2*)(out + (size_t)r0 * DIM + c0) = v;
                }
                if (r1 < N_NODES) {
                    float2 v = make_float2(fmaxf(acc[mi][ni][2] + b0, 0.f),
                                           fmaxf(acc[mi][ni][3] + b1, 0.f));
                    *(float2*)(out + (size_t)r1 * DIM + c0) = v;
                }
            }
        }
    } else {
        float* part = sm;

        float wl0[8], wl1[8], wr0[8], wr1[8], bcol[8];
#pragma unroll
        for (int ni = 0; ni < 4; ni++) {
#pragma unroll
            for (int cc = 0; cc < 2; cc++) {
                int j = ni * 2 + cc;
                int c = warp_n + ni * 8 + t * 2 + cc;
                wl0[j] = __ldg(&W3l[c * 2 + 0]);
                wl1[j] = __ldg(&W3l[c * 2 + 1]);
                wr0[j] = __ldg(&W3r[c * 2 + 0]);
                wr1[j] = __ldg(&W3r[c * 2 + 1]);
                bcol[j] = sbias[c];
            }
        }

#pragma unroll
        for (int mi = 0; mi < 4; mi++) {
            float s0p0 = 0.f, s0p1 = 0.f, s0q0 = 0.f, s0q1 = 0.f;
            float s1p0 = 0.f, s1p1 = 0.f, s1q0 = 0.f, s1q1 = 0.f;
#pragma unroll
            for (int ni = 0; ni < 4; ni++) {
                int j0 = ni * 2, j1 = ni * 2 + 1;
                float v0 = fmaxf(acc[mi][ni][0] + bcol[j0], 0.f);
                float v1 = fmaxf(acc[mi][ni][1] + bcol[j1], 0.f);
                float v2 = fmaxf(acc[mi][ni][2] + bcol[j0], 0.f);
                float v3 = fmaxf(acc[mi][ni][3] + bcol[j1], 0.f);
                s0p0 = fmaf(v0, wl0[j0], fmaf(v1, wl0[j1], s0p0));
                s0p1 = fmaf(v0, wl1[j0], fmaf(v1, wl1[j1], s0p1));
                s0q0 = fmaf(v0, wr0[j0], fmaf(v1, wr0[j1], s0q0));
                s0q1 = fmaf(v0, wr1[j0], fmaf(v1, wr1[j1], s0q1));
                s1p0 = fmaf(v2, wl0[j0], fmaf(v3, wl0[j1], s1p0));
                s1p1 = fmaf(v2, wl1[j0], fmaf(v3, wl1[j1], s1p1));
                s1q0 = fmaf(v2, wr0[j0], fmaf(v3, wr0[j1], s1q0));
                s1q1 = fmaf(v2, wr1[j0], fmaf(v3, wr1[j1], s1q1));
            }
#pragma unroll
            for (int off = 1; off < 4; off <<= 1) {
                s0p0 += __shfl_down_sync(0xffffffffu, s0p0, off, 4);
                s0p1 += __shfl_down_sync(0xffffffffu, s0p1, off, 4);
                s0q0 += __shfl_down_sync(0xffffffffu, s0q0, off, 4);
                s0q1 += __shfl_down_sync(0xffffffffu, s0q1, off, 4);
                s1p0 += __shfl_down_sync(0xffffffffu, s1p0, off, 4);
                s1p1 += __shfl_down_sync(0xffffffffu, s1p1, off, 4);
                s1q0 += __shfl_down_sync(0xffffffffu, s1q0, off, 4);
                s1q1 += __shfl_down_sync(0xffffffffu, s1q1, off, 4);
            }
            if (t == 0) {
                int l0 = mi * 16 + g;
                float* pr0 = part + (wid * 64 + l0) * 4;
                pr0[0] = s0p0; pr0[1] = s0p1; pr0[2] = s0q0; pr0[3] = s0q1;
                float* pr1 = part + (wid * 64 + l0 + 8) * 4;
                pr1[0] = s1p0; pr1[1] = s1p1; pr1[2] = s1q0; pr1[3] = s1q1;
            }
        }
        __syncthreads();

        for (int idx = tid; idx < 512; idx += 256) {
            int rl = idx >> 2, v = idx & 3;
            int grp = rl >> 6;
            int l64 = rl & 63;
            float s = 0.f;
#pragma unroll
            for (int w = 0; w < 4; w++)
                s += part[((grp * 4 + w) * 64 + l64) * 4 + v];
            int node = row_base + rl;
            if (node < N_NODES) {
                if (v < 2) p_out[node * 2 + v] = s;
                else       q_out[node * 2 + (v - 2)] = s + __ldg(&b3[v - 2]);
            }
        }
    }
}

// ---------------- layer-3 gather + relu + log_softmax ------------------------
__global__ void k_final(float* __restrict__ out) {
    int warp = (blockIdx.x * blockDim.x + threadIdx.x) >> 5;
    int lane = threadIdx.x & 31;
    if (warp >= N_NODES) return;
    int s0 = g_rowptr[warp];
    int s1 = g_rowptr[warp + 1];
    float a0 = 0.f, a1 = 0.f;
    for (int e = s0 + lane; e < s1; e += 32) {
        int s = __ldg(&g_perm[e]);
        a0 += g_p[s * 2 + 0];
        a1 += g_p[s * 2 + 1];
    }
#pragma unroll
    for (int off = 16; off > 0; off >>= 1) {
        a0 += __shfl_down_sync(0xffffffffu, a0, off);
        a1 += __shfl_down_sync(0xffffffffu, a1, off);
    }
    if (lane == 0) {
        float di = g_deginv[warp];
        float v0 = fmaxf(a0 * di + g_q[warp * 2 + 0], 0.f);
        float v1 = fmaxf(a1 * di + g_q[warp * 2 + 1], 0.f);
        float m = fmaxf(v0, v1);
        float lse = m + logf(expf(v0 - m) + expf(v1 - m));
        out[warp * 2 + 0] = v0 - lse;
        out[warp * 2 + 1] = v1 - lse;
    }
}

// ---------------- launch -----------------------------------------------------
extern "C" void kernel_launch(void* const* d_in, const int* in_sizes, int n_in,
                              void* d_out, int out_size) {
    const float* x   = (const float*)d_in[0];
    const void*  ei  = d_in[1];
    const float* W1l = (const float*)d_in[2];
    const float* W1r = (const float*)d_in[3];
    const float* b1  = (const float*)d_in[4];
    const float* W2l = (const float*)d_in[5];
    const float* W2r = (const float*)d_in[6];
    const float* b2  = (const float*)d_in[7];
    const float* W3l = (const float*)d_in[8];
    const float* W3r = (const float*)d_in[9];
    const float* b3  = (const float*)d_in[10];
    float* out = (float*)d_out;

    const int QUAD_BLOCKS = (N_EDGES / 4 + 255) / 256;
    const int NODE_BLOCKS = (N_NODES + 255) / 256;
    const int WARP_BLOCKS = (N_NODES * 32 + 255) / 256;

    float* agg; cudaGetSymbolAddress((void**)&agg, g_agg);
    float* h1;  cudaGetSymbolAddress((void**)&h1,  g_h1);
    float* wt1; cudaGetSymbolAddress((void**)&wt1, g_wt1);
    float* wt2; cudaGetSymbolAddress((void**)&wt2, g_wt2);
    float* p;   cudaGetSymbolAddress((void**)&p,   g_p);
    float* q;   cudaGetSymbolAddress((void**)&q,   g_q);

    cudaFuncSetAttribute(k_gemm_mma, cudaFuncAttributeMaxDynamicSharedMemorySize, GSM_BYTES);

    // aux stream + events (created once; host-side only, no device allocation)
    static cudaStream_t s1 = nullptr;
    static cudaEvent_t ev_g[2 * NCHUNK], ev_l[2];
    static int init_done = 0;
    if (!init_done) {
        if (cudaStreamCreateWithFlags(&s1, cudaStreamNonBlocking) != cudaSuccess)
            s1 = nullptr;
        for (int i = 0; i < 2 * NCHUNK; i++)
            cudaEventCreateWithFlags(&ev_g[i], cudaEventDisableTiming);
        for (int i = 0; i < 2; i++)
            cudaEventCreateWithFlags(&ev_l[i], cudaEventDisableTiming);
        init_done = 1;
    }
    cudaStream_t sW = s1 ? s1 : (cudaStream_t)0;   // fallback: sequential

    // chunk boundaries in GEMM blocks (multiples of 128 nodes)
    const int blk_off[NCHUNK + 1] = {0, 196, 392, 588, GEMM_BLOCKS_TOTAL};

    // weight prep on aux stream (independent of CSR)
    k_wt<<<(128 * 128 + 255) / 256, 256, 0, sW>>>(W1l, W1r, wt1);
    k_wt<<<(128 * 128 + 255) / 256, 256, 0, sW>>>(W2l, W2r, wt2);

    // CSR build on main stream
    k_zero_counts<<<NODE_BLOCKS, 256>>>((const int*)ei);
    k_hist<<<QUAD_BLOCKS, 256>>>(ei);
    k_scan_a<<<NBLK, SCAN_BLK>>>();
    k_scan_c<<<NBLK, SCAN_BLK>>>();
    k_perm<<<QUAD_BLOCKS, 256>>>(ei);

    // ---- layer 1: pipelined gather (main) / gemm (aux) ----
    for (int c = 0; c < NCHUNK; c++) {
        int n0 = blk_off[c] * 128;
        int n1 = blk_off[c + 1] * 128; if (n1 > N_NODES) n1 = N_NODES;
        int nwarps = n1 - n0;
        k_gather<<<(nwarps * 32 + 255) / 256, 256>>>(x, agg, n0, n1);
        cudaEventRecord(ev_g[c], 0);
        if (s1) cudaStreamWaitEvent(s1, ev_g[c], 0);
        k_gemm_mma<<<blk_off[c + 1] - blk_off[c], 256, GSM_BYTES, sW>>>(
            agg, x, wt1, b1, h1, W3l, W3r, b3, p, q, 0, blk_off[c]);
    }
    cudaEventRecord(ev_l[0], sW);
    cudaStreamWaitEvent((cudaStream_t)0, ev_l[0], 0);

    // ---- layer 2 (+ fused layer-3 projection): pipelined ----
    for (int c = 0; c < NCHUNK; c++) {
        int n0 = blk_off[c] * 128;
        int n1 = blk_off[c + 1] * 128; if (n1 > N_NODES) n1 = N_NODES;
        int nwarps = n1 - n0;
        k_gather<<<(nwarps * 32 + 255) / 256, 256>>>(h1, agg, n0, n1);
        cudaEventRecord(ev_g[NCHUNK + c], 0);
        if (s1) cudaStreamWaitEvent(s1, ev_g[NCHUNK + c], 0);
        k_gemm_mma<<<blk_off[c + 1] - blk_off[c], 256, GSM_BYTES, sW>>>(
            agg, h1, wt2, b2, h1, W3l, W3r, b3, p, q, 1, blk_off[c]);
    }
    cudaEventRecord(ev_l[1], sW);
    cudaStreamWaitEvent((cudaStream_t)0, ev_l[1], 0);

    // ---- layer 3 aggregation + log_softmax ----
    k_final<<<WARP_BLOCKS, 256>>>(out);
}

// round 16
// speedup vs baseline: 1.0982x; 1.0982x over previous
#include <cuda_runtime.h>
#include <cuda_bf16.h>
#include <cuda_fp16.h>
#include <math.h>
#include <stdint.h>

#define N_NODES 100000
#define N_EDGES 1600000
#define DIM 128
#define SCAN_BLK 1024
#define NBLK ((N_NODES + SCAN_BLK - 1) / SCAN_BLK)   // 98

// ---------------- scratch (device globals; no allocations allowed) -------------
__device__ int    g_is64;
__device__ int    g_cnt[N_NODES];
__device__ int    g_cur[N_NODES];
__device__ int    g_tmp[N_NODES];
__device__ int    g_blocksum[128];
__device__ int    g_rowptr[N_NODES + 1];
__device__ int    g_perm[N_EDGES];
__device__ float  g_deginv[N_NODES];
__device__ float  g_agg[(size_t)N_NODES * DIM];
__device__ float  g_h1[(size_t)N_NODES * DIM];
__device__ __half g_xh[(size_t)N_NODES * DIM];
__device__ __half g_h1h[(size_t)N_NODES * DIM];
__device__ float  g_wt1[128 * 256];
__device__ float  g_wt2[128 * 256];
__device__ float  g_p[N_NODES * 2];
__device__ float  g_q[N_NODES * 2];

__device__ __forceinline__ float cvt_tf32(float x) {
    float r; asm("cvt.rna.tf32.f32 %0, %1;" : "=f"(r) : "f"(x)); return r;
}

// ---------------- CSR build --------------------------------------------------
__global__ void k_zero_counts(const int* __restrict__ ei32) {
    int i = blockIdx.x * blockDim.x + threadIdx.x;
    if (i < N_NODES) { g_cnt[i] = 0; g_cur[i] = 0; }
    if (blockIdx.x == 0) {
        __shared__ int nz;
        if (threadIdx.x == 0) nz = 0;
        __syncthreads();
        for (int j = threadIdx.x; j < 4096; j += blockDim.x)
            if (ei32[2 * j + 1] != 0) nz = 1;
        __syncthreads();
        if (threadIdx.x == 0) g_is64 = (nz == 0) ? 1 : 0;
    }
}

__global__ void k_hist(const void* __restrict__ ei) {
    int q = blockIdx.x * blockDim.x + threadIdx.x;
    int e0 = q * 4;
    if (e0 >= N_EDGES) return;
    if (g_is64) {
        const long long* p = (const long long*)ei + N_EDGES + e0;
        atomicAdd(&g_cnt[(int)p[0]], 1);
        atomicAdd(&g_cnt[(int)p[1]], 1);
        atomicAdd(&g_cnt[(int)p[2]], 1);
        atomicAdd(&g_cnt[(int)p[3]], 1);
    } else {
        int4 d = ((const int4*)((const int*)ei + N_EDGES))[q];
        atomicAdd(&g_cnt[d.x], 1);
        atomicAdd(&g_cnt[d.y], 1);
        atomicAdd(&g_cnt[d.z], 1);
        atomicAdd(&g_cnt[d.w], 1);
    }
}

__global__ void k_scan_a() {
    __shared__ int wsum[32];
    int tid = threadIdx.x;
    int lane = tid & 31, warp = tid >> 5;
    int i = blockIdx.x * SCAN_BLK + tid;
    int v = (i < N_NODES) ? g_cnt[i] : 0;
    int x = v;
#pragma unroll
    for (int off = 1; off < 32; off <<= 1) {
        int y = __shfl_up_sync(0xffffffffu, x, off);
        if (lane >= off) x += y;
    }
    if (lane == 31) wsum[warp] = x;
    __syncthreads();
    if (warp == 0) {
        int w = wsum[lane];
        int xw = w;
#pragma unroll
        for (int off = 1; off < 32; off <<= 1) {
            int y = __shfl_up_sync(0xffffffffu, xw, off);
            if (lane >= off) xw += y;
        }
        wsum[lane] = xw - w;
    }
    __syncthreads();
    int excl = x - v + wsum[warp];
    if (i < N_NODES) g_tmp[i] = excl;
    if (tid == SCAN_BLK - 1) g_blocksum[blockIdx.x] = excl + v;
}

__global__ void k_scan_c() {
    __shared__ int wred[32];
    __shared__ int sboff;
    int tid = threadIdx.x;
    int lane = tid & 31, warp = tid >> 5;
    int part = (tid < blockIdx.x) ? g_blocksum[tid] : 0;
#pragma unroll
    for (int off = 16; off > 0; off >>= 1)
        part += __shfl_down_sync(0xffffffffu, part, off);
    if (lane == 0) wred[warp] = part;
    __syncthreads();
    if (warp == 0) {
        int s = wred[lane];
#pragma unroll
        for (int off = 16; off > 0; off >>= 1)
            s += __shfl_down_sync(0xffffffffu, s, off);
        if (lane == 0) sboff = s;
    }
    __syncthreads();
    int i = blockIdx.x * SCAN_BLK + tid;
    if (i < N_NODES) {
        g_rowptr[i] = g_tmp[i] + sboff;
        g_deginv[i] = 1.0f / (float)max(g_cnt[i], 1);
    }
    if (i == 0) g_rowptr[N_NODES] = N_EDGES;
}

__global__ void k_perm(const void* __restrict__ ei) {
    int q = blockIdx.x * blockDim.x + threadIdx.x;
    int e0 = q * 4;
    if (e0 >= N_EDGES) return;
    if (g_is64) {
        const long long* ps = (const long long*)ei + e0;
        const long long* pd = (const long long*)ei + N_EDGES + e0;
#pragma unroll
        for (int j = 0; j < 4; j++) {
            int s = (int)ps[j], d = (int)pd[j];
            int pos = g_rowptr[d] + atomicAdd(&g_cur[d], 1);
            g_perm[pos] = s;
        }
    } else {
        int4 sv = ((const int4*)ei)[q];
        int4 dv = ((const int4*)((const int*)ei + N_EDGES))[q];
        int ss[4] = {sv.x, sv.y, sv.z, sv.w};
        int dd[4] = {dv.x, dv.y, dv.z, dv.w};
#pragma unroll
        for (int j = 0; j < 4; j++) {
            int pos = g_rowptr[dd[j]] + atomicAdd(&g_cur[dd[j]], 1);
            g_perm[pos] = ss[j];
        }
    }
}

// ---------------- x -> fp16 staging copy --------------------------------------
__global__ void k_xh(const float* __restrict__ x, __half* __restrict__ xh) {
    int i = blockIdx.x * blockDim.x + threadIdx.x;
    if (i < N_NODES * DIM / 4) {
        float4 v = ((const float4*)x)[i];
        __half2 h0 = __floats2half2_rn(v.x, v.y);
        __half2 h1 = __floats2half2_rn(v.z, v.w);
        uint2 u;
        u.x = *(uint32_t*)&h0;
        u.y = *(uint32_t*)&h1;
        ((uint2*)xh)[i] = u;
    }
}

// ---------------- weight transpose + stack (tf32 pre-rounded) -----------------
__global__ void k_wt(const float* __restrict__ Wl, const float* __restrict__ Wr,
                     float* __restrict__ Wt) {
    int idx = blockIdx.x * blockDim.x + threadIdx.x;
    if (idx < 128 * 128) {
        int k = idx >> 7, n = idx & 127;
        Wt[n * 256 + k]       = cvt_tf32(Wl[k * 128 + n]);
        Wt[n * 256 + 128 + k] = cvt_tf32(Wr[k * 128 + n]);
    }
}

// ---------------- fp16 gather-aggregate (warp per node, lane owns 4 feats) ----
__global__ void k_gather_h(const __half* __restrict__ feat, float* __restrict__ out) {
    int warp = (blockIdx.x * blockDim.x + threadIdx.x) >> 5;
    int lane = threadIdx.x & 31;
    if (warp >= N_NODES) return;
    int s0 = g_rowptr[warp];
    int s1 = g_rowptr[warp + 1];
    float a0 = 0.f, a1 = 0.f, a2 = 0.f, a3 = 0.f;
    int e = s0;
    for (; e + 1 < s1; e += 2) {
        int sa = __ldg(&g_perm[e]);
        int sb = __ldg(&g_perm[e + 1]);
        float2 ra = *(const float2*)(feat + (size_t)sa * DIM + lane * 4);
        float2 rb = *(const float2*)(feat + (size_t)sb * DIM + lane * 4);
        float2 fa0 = __half22float2(*(__half2*)&ra.x);
        float2 fa1 = __half22float2(*(__half2*)&ra.y);
        float2 fb0 = __half22float2(*(__half2*)&rb.x);
        float2 fb1 = __half22float2(*(__half2*)&rb.y);
        a0 += fa0.x + fb0.x; a1 += fa0.y + fb0.y;
        a2 += fa1.x + fb1.x; a3 += fa1.y + fb1.y;
    }
    if (e < s1) {
        int sa = __ldg(&g_perm[e]);
        float2 ra = *(const float2*)(feat + (size_t)sa * DIM + lane * 4);
        float2 fa0 = __half22float2(*(__half2*)&ra.x);
        float2 fa1 = __half22float2(*(__half2*)&ra.y);
        a0 += fa0.x; a1 += fa0.y; a2 += fa1.x; a3 += fa1.y;
    }
    float di = g_deginv[warp];
    float4 o;
    o.x = cvt_tf32(a0 * di); o.y = cvt_tf32(a1 * di);
    o.z = cvt_tf32(a2 * di); o.w = cvt_tf32(a3 * di);
    *(float4*)(out + (size_t)warp * DIM + lane * 4) = o;
}

// ---------------- tf32 mma.sync GEMM with cp.async double buffering ----------
#define ASTRIDE 36
#define BUF_FLOATS (128 * ASTRIDE)
#define GSM_FLOATS (4 * BUF_FLOATS + 128)
#define GSM_BYTES (GSM_FLOATS * 4)

__device__ __forceinline__ void cp16(uint32_t dst, const void* src, uint32_t srcsz) {
    asm volatile("cp.async.ca.shared.global [%0], [%1], 16, %2;"
                 :: "r"(dst), "l"(src), "r"(srcsz) : "memory");
}
__device__ __forceinline__ void cp_commit() {
    asm volatile("cp.async.commit_group;" ::: "memory");
}
template <int N>
__device__ __forceinline__ void cp_wait() {
    asm volatile("cp.async.wait_group %0;" :: "n"(N) : "memory");
}

__device__ __forceinline__ void mma_tf32(float* c, uint32_t a0, uint32_t a1,
                                         uint32_t a2, uint32_t a3,
                                         uint32_t b0, uint32_t b1) {
    asm volatile(
        "mma.sync.aligned.m16n8k8.row.col.f32.tf32.tf32.f32 "
        "{%0,%1,%2,%3}, {%4,%5,%6,%7}, {%8,%9}, {%0,%1,%2,%3};"
        : "+f"(c[0]), "+f"(c[1]), "+f"(c[2]), "+f"(c[3])
        : "r"(a0), "r"(a1), "r"(a2), "r"(a3), "r"(b0), "r"(b1));
}

__global__ void __launch_bounds__(256, 2)
k_gemm_mma(const float* __restrict__ Aagg, const float* __restrict__ Ax,
           const float* __restrict__ Wt, const float* __restrict__ bias,
           float* __restrict__ out, __half* __restrict__ hh_out,
           const float* __restrict__ W3l, const float* __restrict__ W3r,
           const float* __restrict__ b3,
           float* __restrict__ p_out, float* __restrict__ q_out,
           int fuse_pq) {
    extern __shared__ float sm[];
    float* Abuf = sm;
    float* Bbuf = sm + 2 * BUF_FLOATS;
    float* sbias = sm + 4 * BUF_FLOATS;

    int tid = threadIdx.x;
    int wid = tid >> 5, lane = tid & 31;
    int g = lane >> 2, t = lane & 3;
    int warp_m = (wid >> 2) * 64;
    int warp_n = (wid & 3) * 32;
    int row_base = blockIdx.x * 128;

    if (tid < 128) sbias[tid] = bias[tid];

    uint32_t a_sm_base = (uint32_t)__cvta_generic_to_shared(Abuf);
    uint32_t b_sm_base = (uint32_t)__cvta_generic_to_shared(Bbuf);

    int lrow[4], lseg[4];
#pragma unroll
    for (int i = 0; i < 4; i++) {
        int f = tid + i * 256;
        lrow[i] = f >> 3;
        lseg[i] = f & 7;
    }

    auto issue = [&](int ch, int s) {
        int k0 = ch * 32;
        const float* Asrc = (k0 < 128) ? Aagg : Ax;
        int kbase = k0 & 127;
        uint32_t ao = a_sm_base + (uint32_t)(s * BUF_FLOATS * 4);
        uint32_t bo = b_sm_base + (uint32_t)(s * BUF_FLOATS * 4);
#pragma unroll
        for (int i = 0; i < 4; i++) {
            int row = lrow[i], seg = lseg[i];
            int gr = row_base + row;
            int ok = gr < N_NODES;
            const float* src = Asrc + (size_t)(ok ? gr : 0) * DIM + kbase + seg * 4;
            cp16(ao + (uint32_t)((row * ASTRIDE + seg * 4) * 4), src, ok ? 16u : 0u);
        }
#pragma unroll
        for (int i = 0; i < 4; i++) {
            int row = lrow[i], seg = lseg[i];
            const float* src = Wt + (size_t)row * 256 + k0 + seg * 4;
            cp16(bo + (uint32_t)((row * ASTRIDE + seg * 4) * 4), src, 16u);
        }
        cp_commit();
    };

    float acc[4][4][4];
#pragma unroll
    for (int i = 0; i < 4; i++)
#pragma unroll
        for (int j = 0; j < 4; j++)
#pragma unroll
            for (int q = 0; q < 4; q++) acc[i][j][q] = 0.f;

    issue(0, 0);

    for (int ch = 0; ch < 8; ch++) {
        int s = ch & 1;
        if (ch < 7) issue(ch + 1, s ^ 1);
        if (ch < 7) cp_wait<1>(); else cp_wait<0>();
        __syncthreads();

        const float* As = Abuf + s * BUF_FLOATS;
        const float* Bs = Bbuf + s * BUF_FLOATS;
#pragma unroll
        for (int kk = 0; kk < 4; kk++) {
            int kof = kk * 8;
            uint32_t af[4][4];
#pragma unroll
            for (int mi = 0; mi < 4; mi++) {
                const float* ap = As + (warp_m + mi * 16 + g) * ASTRIDE + kof + t;
                af[mi][0] = __float_as_uint(ap[0]);
                af[mi][1] = __float_as_uint(ap[8 * ASTRIDE]);
                af[mi][2] = __float_as_uint(ap[4]);
                af[mi][3] = __float_as_uint(ap[8 * ASTRIDE + 4]);
            }
            uint32_t bf[4][2];
#pragma unroll
            for (int ni = 0; ni < 4; ni++) {
                const float* bp = Bs + (warp_n + ni * 8 + g) * ASTRIDE + kof + t;
                bf[ni][0] = __float_as_uint(bp[0]);
                bf[ni][1] = __float_as_uint(bp[4]);
            }
#pragma unroll
            for (int mi = 0; mi < 4; mi++)
#pragma unroll
                for (int ni = 0; ni < 4; ni++)
                    mma_tf32(acc[mi][ni], af[mi][0], af[mi][1], af[mi][2], af[mi][3],
                             bf[ni][0], bf[ni][1]);
        }
        __syncthreads();
    }

    if (!fuse_pq) {
        // epilogue: bias + relu; store fp32 h1 (GEMM-2 self term) + fp16 copy
        // (layer-2 gather input)
#pragma unroll
        for (int mi = 0; mi < 4; mi++) {
            int r0 = row_base + warp_m + mi * 16 + g;
            int r1 = r0 + 8;
#pragma unroll
            for (int ni = 0; ni < 4; ni++) {
                int c0 = warp_n + ni * 8 + t * 2;
                float b0 = sbias[c0], b1 = sbias[c0 + 1];
                if (r0 < N_NODES) {
                    float2 v = make_float2(fmaxf(acc[mi][ni][0] + b0, 0.f),
                                           fmaxf(acc[mi][ni][1] + b1, 0.f));
                    *(float2*)(out + (size_t)r0 * DIM + c0) = v;
                    __half2 h = __floats2half2_rn(v.x, v.y);
                    *(__half2*)(hh_out + (size_t)r0 * DIM + c0) = h;
                }
                if (r1 < N_NODES) {
                    float2 v = make_float2(fmaxf(acc[mi][ni][2] + b0, 0.f),
                                           fmaxf(acc[mi][ni][3] + b1, 0.f));
                    *(float2*)(out + (size_t)r1 * DIM + c0) = v;
                    __half2 h = __floats2half2_rn(v.x, v.y);
                    *(__half2*)(hh_out + (size_t)r1 * DIM + c0) = h;
                }
            }
        }
    } else {
        // fused epilogue: h = relu(acc + bias); p = h@W3l, q = h@W3r (+b3)
        float* part = sm;

        float wl0[8], wl1[8], wr0[8], wr1[8], bcol[8];
#pragma unroll
        for (int ni = 0; ni < 4; ni++) {
#pragma unroll
            for (int cc = 0; cc < 2; cc++) {
                int j = ni * 2 + cc;
                int c = warp_n + ni * 8 + t * 2 + cc;
                wl0[j] = __ldg(&W3l[c * 2 + 0]);
                wl1[j] = __ldg(&W3l[c * 2 + 1]);
                wr0[j] = __ldg(&W3r[c * 2 + 0]);
                wr1[j] = __ldg(&W3r[c * 2 + 1]);
                bcol[j] = sbias[c];
            }
        }

#pragma unroll
        for (int mi = 0; mi < 4; mi++) {
            float s0p0 = 0.f, s0p1 = 0.f, s0q0 = 0.f, s0q1 = 0.f;
            float s1p0 = 0.f, s1p1 = 0.f, s1q0 = 0.f, s1q1 = 0.f;
#pragma unroll
            for (int ni = 0; ni < 4; ni++) {
                int j0 = ni * 2, j1 = ni * 2 + 1;
                float v0 = fmaxf(acc[mi][ni][0] + bcol[j0], 0.f);
                float v1 = fmaxf(acc[mi][ni][1] + bcol[j1], 0.f);
                float v2 = fmaxf(acc[mi][ni][2] + bcol[j0], 0.f);
                float v3 = fmaxf(acc[mi][ni][3] + bcol[j1], 0.f);
                s0p0 = fmaf(v0, wl0[j0], fmaf(v1, wl0[j1], s0p0));
                s0p1 = fmaf(v0, wl1[j0], fmaf(v1, wl1[j1], s0p1));
                s0q0 = fmaf(v0, wr0[j0], fmaf(v1, wr0[j1], s0q0));
                s0q1 = fmaf(v0, wr1[j0], fmaf(v1, wr1[j1], s0q1));
                s1p0 = fmaf(v2, wl0[j0], fmaf(v3, wl0[j1], s1p0));
                s1p1 = fmaf(v2, wl1[j0], fmaf(v3, wl1[j1], s1p1));
                s1q0 = fmaf(v2, wr0[j0], fmaf(v3, wr0[j1], s1q0));
                s1q1 = fmaf(v2, wr1[j0], fmaf(v3, wr1[j1], s1q1));
            }
#pragma unroll
            for (int off = 1; off < 4; off <<= 1) {
                s0p0 += __shfl_down_sync(0xffffffffu, s0p0, off, 4);
                s0p1 += __shfl_down_sync(0xffffffffu, s0p1, off, 4);
                s0q0 += __shfl_down_sync(0xffffffffu, s0q0, off, 4);
                s0q1 += __shfl_down_sync(0xffffffffu, s0q1, off, 4);
                s1p0 += __shfl_down_sync(0xffffffffu, s1p0, off, 4);
                s1p1 += __shfl_down_sync(0xffffffffu, s1p1, off, 4);
                s1q0 += __shfl_down_sync(0xffffffffu, s1q0, off, 4);
                s1q1 += __shfl_down_sync(0xffffffffu, s1q1, off, 4);
            }
            if (t == 0) {
                int l0 = mi * 16 + g;
                float* pr0 = part + (wid * 64 + l0) * 4;
                pr0[0] = s0p0; pr0[1] = s0p1; pr0[2] = s0q0; pr0[3] = s0q1;
                float* pr1 = part + (wid * 64 + l0 + 8) * 4;
                pr1[0] = s1p0; pr1[1] = s1p1; pr1[2] = s1q0; pr1[3] = s1q1;
            }
        }
        __syncthreads();

        for (int idx = tid; idx < 512; idx += 256) {
            int rl = idx >> 2, v = idx & 3;
            int grp = rl >> 6;
            int l64 = rl & 63;
            float s = 0.f;
#pragma unroll
            for (int w = 0; w < 4; w++)
                s += part[((grp * 4 + w) * 64 + l64) * 4 + v];
            int node = row_base + rl;
            if (node < N_NODES) {
                if (v < 2) p_out[node * 2 + v] = s;
                else       q_out[node * 2 + (v - 2)] = s + __ldg(&b3[v - 2]);
            }
        }
    }
}

// ---------------- layer-3 gather + relu + log_softmax ------------------------
__global__ void k_final(float* __restrict__ out) {
    int warp = (blockIdx.x * blockDim.x + threadIdx.x) >> 5;
    int lane = threadIdx.x & 31;
    if (warp >= N_NODES) return;
    int s0 = g_rowptr[warp];
    int s1 = g_rowptr[warp + 1];
    float a0 = 0.f, a1 = 0.f;
    for (int e = s0 + lane; e < s1; e += 32) {
        int s = __ldg(&g_perm[e]);
        a0 += g_p[s * 2 + 0];
        a1 += g_p[s * 2 + 1];
    }
#pragma unroll
    for (int off = 16; off > 0; off >>= 1) {
        a0 += __shfl_down_sync(0xffffffffu, a0, off);
        a1 += __shfl_down_sync(0xffffffffu, a1, off);
    }
    if (lane == 0) {
        float di = g_deginv[warp];
        float v0 = fmaxf(a0 * di + g_q[warp * 2 + 0], 0.f);
        float v1 = fmaxf(a1 * di + g_q[warp * 2 + 1], 0.f);
        float m = fmaxf(v0, v1);
        float lse = m + logf(expf(v0 - m) + expf(v1 - m));
        out[warp * 2 + 0] = v0 - lse;
        out[warp * 2 + 1] = v1 - lse;
    }
}

// ---------------- launch -----------------------------------------------------
extern "C" void kernel_launch(void* const* d_in, const int* in_sizes, int n_in,
                              void* d_out, int out_size) {
    const float* x   = (const float*)d_in[0];
    const void*  ei  = d_in[1];
    const float* W1l = (const float*)d_in[2];
    const float* W1r = (const float*)d_in[3];
    const float* b1  = (const float*)d_in[4];
    const float* W2l = (const float*)d_in[5];
    const float* W2r = (const float*)d_in[6];
    const float* b2  = (const float*)d_in[7];
    const float* W3l = (const float*)d_in[8];
    const float* W3r = (const float*)d_in[9];
    const float* b3  = (const float*)d_in[10];
    float* out = (float*)d_out;

    const int QUAD_BLOCKS = (N_EDGES / 4 + 255) / 256;
    const int NODE_BLOCKS = (N_NODES + 255) / 256;
    const int WARP_BLOCKS = (N_NODES * 32 + 255) / 256;
    const int GEMM_BLOCKS = (N_NODES + 127) / 128;       // 782
    const int XH_BLOCKS = (N_NODES * DIM / 4 + 255) / 256;

    float*  agg; cudaGetSymbolAddress((void**)&agg, g_agg);
    float*  h1;  cudaGetSymbolAddress((void**)&h1,  g_h1);
    __half* xh;  cudaGetSymbolAddress((void**)&xh,  g_xh);
    __half* h1h; cudaGetSymbolAddress((void**)&h1h, g_h1h);
    float*  wt1; cudaGetSymbolAddress((void**)&wt1, g_wt1);
    float*  wt2; cudaGetSymbolAddress((void**)&wt2, g_wt2);
    float*  p;   cudaGetSymbolAddress((void**)&p,   g_p);
    float*  q;   cudaGetSymbolAddress((void**)&q,   g_q);

    cudaFuncSetAttribute(k_gemm_mma, cudaFuncAttributeMaxDynamicSharedMemorySize, GSM_BYTES);

    // CSR build + staging + weight prep (single stream — R14 showed overlap hurts)
    k_zero_counts<<<NODE_BLOCKS, 256>>>((const int*)ei);
    k_hist<<<QUAD_BLOCKS, 256>>>(ei);
    k_scan_a<<<NBLK, SCAN_BLK>>>();
    k_scan_c<<<NBLK, SCAN_BLK>>>();
    k_perm<<<QUAD_BLOCKS, 256>>>(ei);
    k_xh<<<XH_BLOCKS, 256>>>(x, xh);
    k_wt<<<(128 * 128 + 255) / 256, 256>>>(W1l, W1r, wt1);
    k_wt<<<(128 * 128 + 255) / 256, 256>>>(W2l, W2r, wt2);

    // layer 1 (fp16 gather input; fp32 self term)
    k_gather_h<<<WARP_BLOCKS, 256>>>(xh, agg);
    k_gemm_mma<<<GEMM_BLOCKS, 256, GSM_BYTES>>>(agg, x, wt1, b1, h1, h1h,
                                                W3l, W3r, b3, p, q, 0);

    // layer 2 + fused layer-3 projection
    k_gather_h<<<WARP_BLOCKS, 256>>>(h1h, agg);
    k_gemm_mma<<<GEMM_BLOCKS, 256, GSM_BYTES>>>(agg, h1, wt2, b2, h1, h1h,
                                                W3l, W3r, b3, p, q, 1);

    // layer 3 aggregation + log_softmax
    k_final<<<WARP_BLOCKS, 256>>>(out);
}

// round 17
// speedup vs baseline: 1.2916x; 1.1761x over previous
#include <cuda_runtime.h>
#include <cuda_bf16.h>
#include <cuda_fp16.h>
#include <math.h>
#include <stdint.h>

#define N_NODES 100000
#define N_EDGES 1600000
#define DIM 128
#define SCAN_BLK 1024
#define NBLK ((N_NODES + SCAN_BLK - 1) / SCAN_BLK)   // 98

// ---------------- scratch (device globals; no allocations allowed) -------------
__device__ int    g_is64;
__device__ int    g_cnt[N_NODES];
__device__ int    g_cur[N_NODES];
__device__ int    g_tmp[N_NODES];
__device__ int    g_blocksum[128];
__device__ int    g_rowptr[N_NODES + 1];
__device__ int    g_perm[N_EDGES];
__device__ float  g_deginv[N_NODES];
__device__ __half g_aggh[(size_t)N_NODES * DIM];
__device__ __half g_xh[(size_t)N_NODES * DIM];
__device__ __half g_h1h[(size_t)N_NODES * DIM];
__device__ __half g_wt1h[128 * 256];
__device__ __half g_wt2h[128 * 256];
__device__ float  g_p[N_NODES * 2];
__device__ float  g_q[N_NODES * 2];

// ---------------- CSR build --------------------------------------------------
__global__ void k_zero_counts(const int* __restrict__ ei32) {
    int i = blockIdx.x * blockDim.x + threadIdx.x;
    if (i < N_NODES) { g_cnt[i] = 0; g_cur[i] = 0; }
    if (blockIdx.x == 0) {
        __shared__ int nz;
        if (threadIdx.x == 0) nz = 0;
        __syncthreads();
        for (int j = threadIdx.x; j < 4096; j += blockDim.x)
            if (ei32[2 * j + 1] != 0) nz = 1;
        __syncthreads();
        if (threadIdx.x == 0) g_is64 = (nz == 0) ? 1 : 0;
    }
}

__global__ void k_hist(const void* __restrict__ ei) {
    int q = blockIdx.x * blockDim.x + threadIdx.x;
    int e0 = q * 4;
    if (e0 >= N_EDGES) return;
    if (g_is64) {
        const long long* p = (const long long*)ei + N_EDGES + e0;
        atomicAdd(&g_cnt[(int)p[0]], 1);
        atomicAdd(&g_cnt[(int)p[1]], 1);
        atomicAdd(&g_cnt[(int)p[2]], 1);
        atomicAdd(&g_cnt[(int)p[3]], 1);
    } else {
        int4 d = ((const int4*)((const int*)ei + N_EDGES))[q];
        atomicAdd(&g_cnt[d.x], 1);
        atomicAdd(&g_cnt[d.y], 1);
        atomicAdd(&g_cnt[d.z], 1);
        atomicAdd(&g_cnt[d.w], 1);
    }
}

__global__ void k_scan_a() {
    __shared__ int wsum[32];
    int tid = threadIdx.x;
    int lane = tid & 31, warp = tid >> 5;
    int i = blockIdx.x * SCAN_BLK + tid;
    int v = (i < N_NODES) ? g_cnt[i] : 0;
    int x = v;
#pragma unroll
    for (int off = 1; off < 32; off <<= 1) {
        int y = __shfl_up_sync(0xffffffffu, x, off);
        if (lane >= off) x += y;
    }
    if (lane == 31) wsum[warp] = x;
    __syncthreads();
    if (warp == 0) {
        int w = wsum[lane];
        int xw = w;
#pragma unroll
        for (int off = 1; off < 32; off <<= 1) {
            int y = __shfl_up_sync(0xffffffffu, xw, off);
            if (lane >= off) xw += y;
        }
        wsum[lane] = xw - w;
    }
    __syncthreads();
    int excl = x - v + wsum[warp];
    if (i < N_NODES) g_tmp[i] = excl;
    if (tid == SCAN_BLK - 1) g_blocksum[blockIdx.x] = excl + v;
}

__global__ void k_scan_c() {
    __shared__ int wred[32];
    __shared__ int sboff;
    int tid = threadIdx.x;
    int lane = tid & 31, warp = tid >> 5;
    int part = (tid < blockIdx.x) ? g_blocksum[tid] : 0;
#pragma unroll
    for (int off = 16; off > 0; off >>= 1)
        part += __shfl_down_sync(0xffffffffu, part, off);
    if (lane == 0) wred[warp] = part;
    __syncthreads();
    if (warp == 0) {
        int s = wred[lane];
#pragma unroll
        for (int off = 16; off > 0; off >>= 1)
            s += __shfl_down_sync(0xffffffffu, s, off);
        if (lane == 0) sboff = s;
    }
    __syncthreads();
    int i = blockIdx.x * SCAN_BLK + tid;
    if (i < N_NODES) {
        g_rowptr[i] = g_tmp[i] + sboff;
        g_deginv[i] = 1.0f / (float)max(g_cnt[i], 1);
    }
    if (i == 0) g_rowptr[N_NODES] = N_EDGES;
}

__global__ void k_perm(const void* __restrict__ ei) {
    int q = blockIdx.x * blockDim.x + threadIdx.x;
    int e0 = q * 4;
    if (e0 >= N_EDGES) return;
    if (g_is64) {
        const long long* ps = (const long long*)ei + e0;
        const long long* pd = (const long long*)ei + N_EDGES + e0;
#pragma unroll
        for (int j = 0; j < 4; j++) {
            int s = (int)ps[j], d = (int)pd[j];
            int pos = g_rowptr[d] + atomicAdd(&g_cur[d], 1);
            g_perm[pos] = s;
        }
    } else {
        int4 sv = ((const int4*)ei)[q];
        int4 dv = ((const int4*)((const int*)ei + N_EDGES))[q];
        int ss[4] = {sv.x, sv.y, sv.z, sv.w};
        int dd[4] = {dv.x, dv.y, dv.z, dv.w};
#pragma unroll
        for (int j = 0; j < 4; j++) {
            int pos = g_rowptr[dd[j]] + atomicAdd(&g_cur[dd[j]], 1);
            g_perm[pos] = ss[j];
        }
    }
}

// ---------------- x -> fp16 staging copy --------------------------------------
__global__ void k_xh(const float* __restrict__ x, __half* __restrict__ xh) {
    int i = blockIdx.x * blockDim.x + threadIdx.x;
    if (i < N_NODES * DIM / 4) {
        float4 v = ((const float4*)x)[i];
        __half2 h0 = __floats2half2_rn(v.x, v.y);
        __half2 h1 = __floats2half2_rn(v.z, v.w);
        uint2 u;
        u.x = *(uint32_t*)&h0;
        u.y = *(uint32_t*)&h1;
        ((uint2*)xh)[i] = u;
    }
}

// ---------------- weight transpose + stack -> fp16, Wt[n][k] k=0..255 ---------
__global__ void k_wt(const float* __restrict__ Wl, const float* __restrict__ Wr,
                     __half* __restrict__ Wt) {
    int idx = blockIdx.x * blockDim.x + threadIdx.x;
    if (idx < 128 * 128) {
        int k = idx >> 7, n = idx & 127;
        Wt[n * 256 + k]       = __float2half_rn(Wl[k * 128 + n]);
        Wt[n * 256 + 128 + k] = __float2half_rn(Wr[k * 128 + n]);
    }
}

// ---------------- fp16 gather-aggregate (warp per node, lane owns 4 feats) ----
__global__ void k_gather_h(const __half* __restrict__ feat, __half* __restrict__ out) {
    int warp = (blockIdx.x * blockDim.x + threadIdx.x) >> 5;
    int lane = threadIdx.x & 31;
    if (warp >= N_NODES) return;
    int s0 = g_rowptr[warp];
    int s1 = g_rowptr[warp + 1];
    float a0 = 0.f, a1 = 0.f, a2 = 0.f, a3 = 0.f;
    int e = s0;
    for (; e + 1 < s1; e += 2) {
        int sa = __ldg(&g_perm[e]);
        int sb = __ldg(&g_perm[e + 1]);
        float2 ra = *(const float2*)(feat + (size_t)sa * DIM + lane * 4);
        float2 rb = *(const float2*)(feat + (size_t)sb * DIM + lane * 4);
        float2 fa0 = __half22float2(*(__half2*)&ra.x);
        float2 fa1 = __half22float2(*(__half2*)&ra.y);
        float2 fb0 = __half22float2(*(__half2*)&rb.x);
        float2 fb1 = __half22float2(*(__half2*)&rb.y);
        a0 += fa0.x + fb0.x; a1 += fa0.y + fb0.y;
        a2 += fa1.x + fb1.x; a3 += fa1.y + fb1.y;
    }
    if (e < s1) {
        int sa = __ldg(&g_perm[e]);
        float2 ra = *(const float2*)(feat + (size_t)sa * DIM + lane * 4);
        float2 fa0 = __half22float2(*(__half2*)&ra.x);
        float2 fa1 = __half22float2(*(__half2*)&ra.y);
        a0 += fa0.x; a1 += fa0.y; a2 += fa1.x; a3 += fa1.y;
    }
    float di = g_deginv[warp];
    __half2 h0 = __floats2half2_rn(a0 * di, a1 * di);
    __half2 h1 = __floats2half2_rn(a2 * di, a3 * di);
    uint2 u;
    u.x = *(uint32_t*)&h0;
    u.y = *(uint32_t*)&h1;
    *(uint2*)(out + (size_t)warp * DIM + lane * 4) = u;
}

// ---------------- fp16 mma.sync GEMM with cp.async double buffering ----------
// CTA 128(M)x128(N), 8 warps 2x4, warp tile 64x32. K=256 in 8 chunks of 32.
// mma.m16n8k16.f16 with fp32 accum. smem rows: 32 halves = 16 words + 4 pad
// (HSTRIDE=20 words) -> g*20+t all-distinct banks for fragment LDS.
#define HSTRIDE 20
#define BUF_WORDS (128 * HSTRIDE)                  // 2560 words / 10.24KB
#define GSM_BYTES (4 * BUF_WORDS * 4 + 512)

__device__ __forceinline__ void cp16(uint32_t dst, const void* src, uint32_t srcsz) {
    asm volatile("cp.async.ca.shared.global [%0], [%1], 16, %2;"
                 :: "r"(dst), "l"(src), "r"(srcsz) : "memory");
}
__device__ __forceinline__ void cp_commit() {
    asm volatile("cp.async.commit_group;" ::: "memory");
}
template <int N>
__device__ __forceinline__ void cp_wait() {
    asm volatile("cp.async.wait_group %0;" :: "n"(N) : "memory");
}

__device__ __forceinline__ void mma_f16(float* c, uint32_t a0, uint32_t a1,
                                        uint32_t a2, uint32_t a3,
                                        uint32_t b0, uint32_t b1) {
    asm volatile(
        "mma.sync.aligned.m16n8k16.row.col.f32.f16.f16.f32 "
        "{%0,%1,%2,%3}, {%4,%5,%6,%7}, {%8,%9}, {%0,%1,%2,%3};"
        : "+f"(c[0]), "+f"(c[1]), "+f"(c[2]), "+f"(c[3])
        : "r"(a0), "r"(a1), "r"(a2), "r"(a3), "r"(b0), "r"(b1));
}

__global__ void __launch_bounds__(256, 2)
k_gemm_mma(const __half* __restrict__ Aagg, const __half* __restrict__ Ax,
           const __half* __restrict__ Wt, const float* __restrict__ bias,
           __half* __restrict__ hh_out,
           const float* __restrict__ W3l, const float* __restrict__ W3r,
           const float* __restrict__ b3,
           float* __restrict__ p_out, float* __restrict__ q_out,
           int fuse_pq) {
    extern __shared__ uint32_t smw[];
    uint32_t* Abuf = smw;                       // 2 x BUF_WORDS
    uint32_t* Bbuf = smw + 2 * BUF_WORDS;       // 2 x BUF_WORDS
    float* sbias = (float*)(smw + 4 * BUF_WORDS);   // 128

    int tid = threadIdx.x;
    int wid = tid >> 5, lane = tid & 31;
    int g = lane >> 2, t = lane & 3;
    int warp_m = (wid >> 2) * 64;
    int warp_n = (wid & 3) * 32;
    int row_base = blockIdx.x * 128;

    if (tid < 128) sbias[tid] = bias[tid];

    uint32_t a_sm_base = (uint32_t)__cvta_generic_to_shared(Abuf);
    uint32_t b_sm_base = (uint32_t)__cvta_generic_to_shared(Bbuf);

    // per-thread load coords: 512 segs per tile (128 rows x 4 segs of 16B)
    int lrow[2], lseg[2];
#pragma unroll
    for (int i = 0; i < 2; i++) {
        int f = tid + i * 256;
        lrow[i] = f >> 2;
        lseg[i] = f & 3;
    }

    auto issue = [&](int ch, int s) {
        int k0 = ch * 32;                       // in halves
        const __half* Asrc = (k0 < 128) ? Aagg : Ax;
        int kbase = k0 & 127;
        uint32_t ao = a_sm_base + (uint32_t)(s * BUF_WORDS * 4);
        uint32_t bo = b_sm_base + (uint32_t)(s * BUF_WORDS * 4);
#pragma unroll
        for (int i = 0; i < 2; i++) {
            int row = lrow[i], seg = lseg[i];
            int gr = row_base + row;
            int ok = gr < N_NODES;
            const __half* src = Asrc + (size_t)(ok ? gr : 0) * DIM + kbase + seg * 8;
            cp16(ao + (uint32_t)((row * HSTRIDE + seg * 4) * 4), src, ok ? 16u : 0u);
        }
#pragma unroll
        for (int i = 0; i < 2; i++) {
            int row = lrow[i], seg = lseg[i];
            const __half* src = Wt + (size_t)row * 256 + k0 + seg * 8;
            cp16(bo + (uint32_t)((row * HSTRIDE + seg * 4) * 4), src, 16u);
        }
        cp_commit();
    };

    float acc[4][4][4];
#pragma unroll
    for (int i = 0; i < 4; i++)
#pragma unroll
        for (int j = 0; j < 4; j++)
#pragma unroll
            for (int q = 0; q < 4; q++) acc[i][j][q] = 0.f;

    issue(0, 0);

    for (int ch = 0; ch < 8; ch++) {
        int s = ch & 1;
        if (ch < 7) issue(ch + 1, s ^ 1);
        if (ch < 7) cp_wait<1>(); else cp_wait<0>();
        __syncthreads();

        const uint32_t* As = Abuf + s * BUF_WORDS;
        const uint32_t* Bs = Bbuf + s * BUF_WORDS;
#pragma unroll
        for (int kk = 0; kk < 2; kk++) {         // two k16 steps per 32-chunk
            int kof = kk * 8;                    // word offset
            uint32_t af[4][4];
#pragma unroll
            for (int mi = 0; mi < 4; mi++) {
                const uint32_t* ap = As + (warp_m + mi * 16 + g) * HSTRIDE + kof;
                af[mi][0] = ap[t];
                af[mi][1] = ap[8 * HSTRIDE + t];
                af[mi][2] = ap[t + 4];
                af[mi][3] = ap[8 * HSTRIDE + t + 4];
            }
            uint32_t bf[4][2];
#pragma unroll
            for (int ni = 0; ni < 4; ni++) {
                const uint32_t* bp = Bs + (warp_n + ni * 8 + g) * HSTRIDE + kof;
                bf[ni][0] = bp[t];
                bf[ni][1] = bp[t + 4];
            }
#pragma unroll
            for (int mi = 0; mi < 4; mi++)
#pragma unroll
                for (int ni = 0; ni < 4; ni++)
                    mma_f16(acc[mi][ni], af[mi][0], af[mi][1], af[mi][2], af[mi][3],
                            bf[ni][0], bf[ni][1]);
        }
        __syncthreads();
    }

    if (!fuse_pq) {
        // epilogue: bias + relu; store fp16 h1 only (consumed by gather + GEMM-2)
#pragma unroll
        for (int mi = 0; mi < 4; mi++) {
            int r0 = row_base + warp_m + mi * 16 + g;
            int r1 = r0 + 8;
#pragma unroll
            for (int ni = 0; ni < 4; ni++) {
                int c0 = warp_n + ni * 8 + t * 2;
                float b0 = sbias[c0], b1 = sbias[c0 + 1];
                if (r0 < N_NODES) {
                    __half2 h = __floats2half2_rn(fmaxf(acc[mi][ni][0] + b0, 0.f),
                                                  fmaxf(acc[mi][ni][1] + b1, 0.f));
                    *(__half2*)(hh_out + (size_t)r0 * DIM + c0) = h;
                }
                if (r1 < N_NODES) {
                    __half2 h = __floats2half2_rn(fmaxf(acc[mi][ni][2] + b0, 0.f),
                                                  fmaxf(acc[mi][ni][3] + b1, 0.f));
                    *(__half2*)(hh_out + (size_t)r1 * DIM + c0) = h;
                }
            }
        }
    } else {
        // fused epilogue: h = relu(acc + bias); p = h@W3l, q = h@W3r (+b3)
        float* part = (float*)smw;   // 8*64*4 floats, overlaid on Abuf

        float wl0[8], wl1[8], wr0[8], wr1[8], bcol[8];
#pragma unroll
        for (int ni = 0; ni < 4; ni++) {
#pragma unroll
            for (int cc = 0; cc < 2; cc++) {
                int j = ni * 2 + cc;
                int c = warp_n + ni * 8 + t * 2 + cc;
                wl0[j] = __ldg(&W3l[c * 2 + 0]);
                wl1[j] = __ldg(&W3l[c * 2 + 1]);
                wr0[j] = __ldg(&W3r[c * 2 + 0]);
                wr1[j] = __ldg(&W3r[c * 2 + 1]);
                bcol[j] = sbias[c];
            }
        }

#pragma unroll
        for (int mi = 0; mi < 4; mi++) {
            float s0p0 = 0.f, s0p1 = 0.f, s0q0 = 0.f, s0q1 = 0.f;
            float s1p0 = 0.f, s1p1 = 0.f, s1q0 = 0.f, s1q1 = 0.f;
#pragma unroll
            for (int ni = 0; ni < 4; ni++) {
                int j0 = ni * 2, j1 = ni * 2 + 1;
                float v0 = fmaxf(acc[mi][ni][0] + bcol[j0], 0.f);
                float v1 = fmaxf(acc[mi][ni][1] + bcol[j1], 0.f);
                float v2 = fmaxf(acc[mi][ni][2] + bcol[j0], 0.f);
                float v3 = fmaxf(acc[mi][ni][3] + bcol[j1], 0.f);
                s0p0 = fmaf(v0, wl0[j0], fmaf(v1, wl0[j1], s0p0));
                s0p1 = fmaf(v0, wl1[j0], fmaf(v1, wl1[j1], s0p1));
                s0q0 = fmaf(v0, wr0[j0], fmaf(v1, wr0[j1], s0q0));
                s0q1 = fmaf(v0, wr1[j0], fmaf(v1, wr1[j1], s0q1));
                s1p0 = fmaf(v2, wl0[j0], fmaf(v3, wl0[j1], s1p0));
                s1p1 = fmaf(v2, wl1[j0], fmaf(v3, wl1[j1], s1p1));
                s1q0 = fmaf(v2, wr0[j0], fmaf(v3, wr0[j1], s1q0));
                s1q1 = fmaf(v2, wr1[j0], fmaf(v3, wr1[j1], s1q1));
            }
#pragma unroll
            for (int off = 1; off < 4; off <<= 1) {
                s0p0 += __shfl_down_sync(0xffffffffu, s0p0, off, 4);
                s0p1 += __shfl_down_sync(0xffffffffu, s0p1, off, 4);
                s0q0 += __shfl_down_sync(0xffffffffu, s0q0, off, 4);
                s0q1 += __shfl_down_sync(0xffffffffu, s0q1, off, 4);
                s1p0 += __shfl_down_sync(0xffffffffu, s1p0, off, 4);
                s1p1 += __shfl_down_sync(0xffffffffu, s1p1, off, 4);
                s1q0 += __shfl_down_sync(0xffffffffu, s1q0, off, 4);
                s1q1 += __shfl_down_sync(0xffffffffu, s1q1, off, 4);
            }
            if (t == 0) {
                int l0 = mi * 16 + g;
                float* pr0 = part + (wid * 64 + l0) * 4;
                pr0[0] = s0p0; pr0[1] = s0p1; pr0[2] = s0q0; pr0[3] = s0q1;
                float* pr1 = part + (wid * 64 + l0 + 8) * 4;
                pr1[0] = s1p0; pr1[1] = s1p1; pr1[2] = s1q0; pr1[3] = s1q1;
            }
        }
        __syncthreads();

        for (int idx = tid; idx < 512; idx += 256) {
            int rl = idx >> 2, v = idx & 3;
            int grp = rl >> 6;
            int l64 = rl & 63;
            float s = 0.f;
#pragma unroll
            for (int w = 0; w < 4; w++)
                s += part[((grp * 4 + w) * 64 + l64) * 4 + v];
            int node = row_base + rl;
            if (node < N_NODES) {
                if (v < 2) p_out[node * 2 + v] = s;
                else       q_out[node * 2 + (v - 2)] = s + __ldg(&b3[v - 2]);
            }
        }
    }
}

// ---------------- layer-3 gather + relu + log_softmax ------------------------
__global__ void k_final(float* __restrict__ out) {
    int warp = (blockIdx.x * blockDim.x + threadIdx.x) >> 5;
    int lane = threadIdx.x & 31;
    if (warp >= N_NODES) return;
    int s0 = g_rowptr[warp];
    int s1 = g_rowptr[warp + 1];
    float a0 = 0.f, a1 = 0.f;
    for (int e = s0 + lane; e < s1; e += 32) {
        int s = __ldg(&g_perm[e]);
        a0 += g_p[s * 2 + 0];
        a1 += g_p[s * 2 + 1];
    }
#pragma unroll
    for (int off = 16; off > 0; off >>= 1) {
        a0 += __shfl_down_sync(0xffffffffu, a0, off);
        a1 += __shfl_down_sync(0xffffffffu, a1, off);
    }
    if (lane == 0) {
        float di = g_deginv[warp];
        float v0 = fmaxf(a0 * di + g_q[warp * 2 + 0], 0.f);
        float v1 = fmaxf(a1 * di + g_q[warp * 2 + 1], 0.f);
        float m = fmaxf(v0, v1);
        float lse = m + logf(expf(v0 - m) + expf(v1 - m));
        out[warp * 2 + 0] = v0 - lse;
        out[warp * 2 + 1] = v1 - lse;
    }
}

// ---------------- launch -----------------------------------------------------
extern "C" void kernel_launch(void* const* d_in, const int* in_sizes, int n_in,
                              void* d_out, int out_size) {
    const float* x   = (const float*)d_in[0];
    const void*  ei  = d_in[1];
    const float* W1l = (const float*)d_in[2];
    const float* W1r = (const float*)d_in[3];
    const float* b1  = (const float*)d_in[4];
    const float* W2l = (const float*)d_in[5];
    const float* W2r = (const float*)d_in[6];
    const float* b2  = (const float*)d_in[7];
    const float* W3l = (const float*)d_in[8];
    const float* W3r = (const float*)d_in[9];
    const float* b3  = (const float*)d_in[10];
    float* out = (float*)d_out;

    const int QUAD_BLOCKS = (N_EDGES / 4 + 255) / 256;
    const int NODE_BLOCKS = (N_NODES + 255) / 256;
    const int WARP_BLOCKS = (N_NODES * 32 + 255) / 256;
    const int GEMM_BLOCKS = (N_NODES + 127) / 128;       // 782
    const int XH_BLOCKS = (N_NODES * DIM / 4 + 255) / 256;

    __half* aggh; cudaGetSymbolAddress((void**)&aggh, g_aggh);
    __half* xh;   cudaGetSymbolAddress((void**)&xh,   g_xh);
    __half* h1h;  cudaGetSymbolAddress((void**)&h1h,  g_h1h);
    __half* wt1h; cudaGetSymbolAddress((void**)&wt1h, g_wt1h);
    __half* wt2h; cudaGetSymbolAddress((void**)&wt2h, g_wt2h);
    float*  p;    cudaGetSymbolAddress((void**)&p,    g_p);
    float*  q;    cudaGetSymbolAddress((void**)&q,    g_q);

    cudaFuncSetAttribute(k_gemm_mma, cudaFuncAttributeMaxDynamicSharedMemorySize, GSM_BYTES);

    // CSR build + staging + weight prep (single stream)
    k_zero_counts<<<NODE_BLOCKS, 256>>>((const int*)ei);
    k_hist<<<QUAD_BLOCKS, 256>>>(ei);
    k_scan_a<<<NBLK, SCAN_BLK>>>();
    k_scan_c<<<NBLK, SCAN_BLK>>>();
    k_perm<<<QUAD_BLOCKS, 256>>>(ei);
    k_xh<<<XH_BLOCKS, 256>>>(x, xh);
    k_wt<<<(128 * 128 + 255) / 256, 256>>>(W1l, W1r, wt1h);
    k_wt<<<(128 * 128 + 255) / 256, 256>>>(W2l, W2r, wt2h);

    // layer 1 (all-fp16 operands; fp32 accum)
    k_gather_h<<<WARP_BLOCKS, 256>>>(xh, aggh);
    k_gemm_mma<<<GEMM_BLOCKS, 256, GSM_BYTES>>>(aggh, xh, wt1h, b1, h1h,
                                                W3l, W3r, b3, p, q, 0);

    // layer 2 + fused layer-3 projection
    k_gather_h<<<WARP_BLOCKS, 256>>>(h1h, aggh);
    k_gemm_mma<<<GEMM_BLOCKS, 256, GSM_BYTES>>>(aggh, h1h, wt2h, b2, h1h,
                                                W3l, W3r, b3, p, q, 1);

    // layer 3 aggregation + log_softmax
    k_final<<<WARP_BLOCKS, 256>>>(out);
}